// round 2
// baseline (speedup 1.0000x reference)
#include <cuda_runtime.h>

#define Nn 16384
#define EE 524288
#define CIN 128
#define HH 64
#define KK 64

// ---------------- device scratch (no allocations allowed) ----------------
__device__ float g_xw[Nn*HH];     // x @ W1
__device__ float g_h[Nn*HH];      // relu'd GCN output
__device__ float g_deg[Nn];       // GCN degree (incl. self loop weight 1)
__device__ float g_dis[Nn];       // rsqrt(deg)
__device__ int   g_cnt[Nn];       // in-edge counts (== degadj, column sums of adj)
__device__ int   g_off[Nn+1];     // CSC bucket offsets
__device__ int   g_cur[Nn];       // fill cursors
__device__ int   g_rows[EE];      // source row per CSC slot
__device__ float g_wn[EE];        // normalized edge weight per CSC slot
__device__ float g_ss[KK*KK];     // s^T s
__device__ float g_ca[KK];        // s^T deg_adj
__device__ float g_cs[KK];        // column sums of s
__device__ double g_trace;        // trace(s^T adj s)

// ---------------- init: zero accumulators each replay ----------------
__global__ void k_init() {
    int i = blockIdx.x * blockDim.x + threadIdx.x;
    int stride = gridDim.x * blockDim.x;
    for (int j = i; j < Nn; j += stride) { g_deg[j] = 1.0f; g_cnt[j] = 0; }
    for (int j = i; j < KK*KK; j += stride) g_ss[j] = 0.f;
    if (i < KK) { g_ca[i] = 0.f; g_cs[i] = 0.f; }
    if (i == 0) g_trace = 0.0;
}

// ---------------- xw = x @ W1  (N,128)x(128,64) ----------------
__global__ __launch_bounds__(256) void k_xw(const float* __restrict__ x,
                                            const float* __restrict__ W1) {
    __shared__ float Ws[CIN*HH]; // 32 KB
    for (int j = threadIdx.x; j < CIN*HH; j += blockDim.x) Ws[j] = W1[j];
    __syncthreads();
    int gw = (blockIdx.x * blockDim.x + threadIdx.x) >> 5;
    int lane = threadIdx.x & 31;
    int nw = (gridDim.x * blockDim.x) >> 5;
    for (int r0 = gw * 4; r0 < Nn; r0 += nw * 4) {
        float a00=0,a01=0,a10=0,a11=0,a20=0,a21=0,a30=0,a31=0;
        const float* x0 = x + (size_t)r0 * CIN;
        #pragma unroll 4
        for (int k = 0; k < CIN; k++) {
            float w0 = Ws[k*HH + lane], w1 = Ws[k*HH + lane + 32];
            float x_0 = __ldg(x0 + k);
            float x_1 = __ldg(x0 + CIN + k);
            float x_2 = __ldg(x0 + 2*CIN + k);
            float x_3 = __ldg(x0 + 3*CIN + k);
            a00 += x_0*w0; a01 += x_0*w1;
            a10 += x_1*w0; a11 += x_1*w1;
            a20 += x_2*w0; a21 += x_2*w1;
            a30 += x_3*w0; a31 += x_3*w1;
        }
        float* o = g_xw + (size_t)r0 * HH;
        o[lane] = a00;        o[lane+32] = a01;
        o[HH+lane] = a10;     o[HH+lane+32] = a11;
        o[2*HH+lane] = a20;   o[2*HH+lane+32] = a21;
        o[3*HH+lane] = a30;   o[3*HH+lane+32] = a31;
    }
}

// ---------------- degree + count histograms ----------------
__global__ void k_deg(const int* __restrict__ ei, const float* __restrict__ ew, int E) {
    int i = blockIdx.x * blockDim.x + threadIdx.x;
    int stride = gridDim.x * blockDim.x;
    for (int e = i; e < E; e += stride) {
        int c = ei[E + e];                 // edge_index[1] (target)
        atomicAdd(&g_deg[c], ew[e]);
        atomicAdd(&g_cnt[c], 1);
    }
}

__global__ void k_dis() {
    int i = blockIdx.x * blockDim.x + threadIdx.x;
    if (i < Nn) {
        float d = g_deg[i];
        g_dis[i] = d > 0.f ? rsqrtf(d) : 0.f;
    }
}

// ---------------- exclusive prefix scan of g_cnt (1 block, 1024 thr) ------
__global__ __launch_bounds__(1024) void k_scan() {
    __shared__ int wsum[32];
    int t = threadIdx.x;
    int lane = t & 31, wid = t >> 5;
    int base = t * 16;
    int local[16];
    int s = 0;
    #pragma unroll
    for (int i = 0; i < 16; i++) { local[i] = g_cnt[base + i]; s += local[i]; }
    // inclusive warp scan of s
    int ws = s;
    #pragma unroll
    for (int o = 1; o < 32; o <<= 1) {
        int v = __shfl_up_sync(0xFFFFFFFFu, ws, o);
        if (lane >= o) ws += v;
    }
    if (lane == 31) wsum[wid] = ws;
    __syncthreads();
    if (t < 32) {
        int v = wsum[t];
        #pragma unroll
        for (int o = 1; o < 32; o <<= 1) {
            int u = __shfl_up_sync(0xFFFFFFFFu, v, o);
            if (t >= o) v += u;
        }
        wsum[t] = v;
    }
    __syncthreads();
    int offset = (wid ? wsum[wid - 1] : 0) + ws - s;  // exclusive
    int run = offset;
    #pragma unroll
    for (int i = 0; i < 16; i++) {
        g_off[base + i] = run;
        g_cur[base + i] = run;
        run += local[i];
    }
    if (t == 1023) g_off[Nn] = run;
}

// ---------------- fill CSC buckets: (row, norm) per slot ----------------
__global__ __launch_bounds__(256) void k_fill(const int* __restrict__ ei,
                                              const float* __restrict__ ew, int E) {
    int i = blockIdx.x * blockDim.x + threadIdx.x;
    int stride = gridDim.x * blockDim.x;
    for (int e = i; e < E; e += stride) {
        int r = __ldg(ei + e);
        int c = __ldg(ei + E + e);
        float w = g_dis[r] * __ldg(ew + e) * g_dis[c];
        int pos = atomicAdd(&g_cur[c], 1);
        g_rows[pos] = r;
        g_wn[pos] = w;
    }
}

// ---------------- gather + self loop + bias + relu ----------------
// warp per node; lane owns cols (lane, lane+32)
__global__ __launch_bounds__(256) void k_gather(const float* __restrict__ b1) {
    int gw = (blockIdx.x * blockDim.x + threadIdx.x) >> 5;
    int lane = threadIdx.x & 31;
    int nw = (gridDim.x * blockDim.x) >> 5;
    for (int c = gw; c < Nn; c += nw) {
        int beg = g_off[c], end = g_off[c + 1];
        float dc = g_dis[c];
        float selfw = dc * dc;
        float a0 = g_xw[(size_t)c*HH + lane] * selfw;
        float a1 = g_xw[(size_t)c*HH + lane + 32] * selfw;
        for (int j0 = beg; j0 < end; j0 += 32) {
            int jj = j0 + lane;
            int r = 0; float w = 0.f;
            if (jj < end) { r = g_rows[jj]; w = g_wn[jj]; }
            int cnt = min(32, end - j0);
            for (int k = 0; k < cnt; k++) {
                int rk = __shfl_sync(0xFFFFFFFFu, r, k);
                float wk = __shfl_sync(0xFFFFFFFFu, w, k);
                const float* src = g_xw + (size_t)rk * HH;
                a0 += src[lane] * wk;
                a1 += src[lane + 32] * wk;
            }
        }
        g_h[(size_t)c*HH + lane]      = fmaxf(a0 + b1[lane], 0.f);
        g_h[(size_t)c*HH + lane + 32] = fmaxf(a1 + b1[lane + 32], 0.f);
    }
}

// ---------------- fused MLP + softmax + cs/ca stats ----------------
__global__ __launch_bounds__(256) void k_mlp(const float* __restrict__ Wm1,
                                             const float* __restrict__ bm1,
                                             const float* __restrict__ Wm2,
                                             const float* __restrict__ bm2,
                                             float* __restrict__ out) {
    __shared__ float W1s[HH*HH];  // 16 KB
    __shared__ float W2s[HH*KK];  // 16 KB
    __shared__ float tbuf[8][HH];
    for (int j = threadIdx.x; j < HH*HH; j += blockDim.x) W1s[j] = Wm1[j];
    for (int j = threadIdx.x; j < HH*KK; j += blockDim.x) W2s[j] = Wm2[j];
    __syncthreads();
    int wid = threadIdx.x >> 5;
    int lane = threadIdx.x & 31;
    int gw = blockIdx.x * 8 + wid;
    int nw = gridDim.x * 8;
    int c0 = lane, c1 = lane + 32;
    float b1a = bm1[c0], b1b = bm1[c1];
    float b2a = bm2[c0], b2b = bm2[c1];
    float cs0 = 0.f, cs1 = 0.f, ca0 = 0.f, ca1 = 0.f;
    for (int row = gw; row < Nn; row += nw) {
        const float* hrow = g_h + (size_t)row * HH;
        float t0 = b1a, t1 = b1b;
        #pragma unroll 8
        for (int k = 0; k < HH; k++) {
            float hk = __ldg(hrow + k);
            t0 += hk * W1s[k*HH + c0];
            t1 += hk * W1s[k*HH + c1];
        }
        tbuf[wid][c0] = t0; tbuf[wid][c1] = t1;
        __syncwarp();
        float l0 = b2a, l1 = b2b;
        #pragma unroll 8
        for (int k = 0; k < HH; k++) {
            float tk = tbuf[wid][k];
            l0 += tk * W2s[k*KK + c0];
            l1 += tk * W2s[k*KK + c1];
        }
        __syncwarp();
        float mx = fmaxf(l0, l1);
        #pragma unroll
        for (int o = 16; o; o >>= 1) mx = fmaxf(mx, __shfl_xor_sync(0xFFFFFFFFu, mx, o));
        float e0 = __expf(l0 - mx), e1 = __expf(l1 - mx);
        float sm = e0 + e1;
        #pragma unroll
        for (int o = 16; o; o >>= 1) sm += __shfl_xor_sync(0xFFFFFFFFu, sm, o);
        float inv = 1.0f / sm;
        float s0 = e0 * inv, s1 = e1 * inv;
        out[(size_t)row*KK + c0] = s0;
        out[(size_t)row*KK + c1] = s1;
        cs0 += s0; cs1 += s1;
        float da = (float)g_cnt[row];
        ca0 += s0 * da; ca1 += s1 * da;
    }
    atomicAdd(&g_cs[c0], cs0); atomicAdd(&g_cs[c1], cs1);
    atomicAdd(&g_ca[c0], ca0); atomicAdd(&g_ca[c1], ca1);
}

// ---------------- ss = s^T s (64x64) ----------------
__global__ __launch_bounds__(256) void k_ss(const float* __restrict__ s) {
    __shared__ float srow[KK];
    int t = threadIdx.x;
    int a = t >> 2;
    int b0 = (t & 3) * 16;
    float acc[16];
    #pragma unroll
    for (int j = 0; j < 16; j++) acc[j] = 0.f;
    for (int row = blockIdx.x; row < Nn; row += gridDim.x) {
        if (t < 16) ((float4*)srow)[t] = ((const float4*)(s + (size_t)row*KK))[t];
        __syncthreads();
        float sa = srow[a];
        #pragma unroll
        for (int j = 0; j < 16; j++) acc[j] += sa * srow[b0 + j];
        __syncthreads();
    }
    #pragma unroll
    for (int j = 0; j < 16; j++) atomicAdd(&g_ss[a*KK + b0 + j], acc[j]);
}

// ---------------- trace(s^T adj s) via CSC buckets ----------------
// warp per node c: s[c] kept in registers; only s[row] is a random read.
__global__ __launch_bounds__(256) void k_trace(const float* __restrict__ s) {
    int gw = (blockIdx.x * blockDim.x + threadIdx.x) >> 5;
    int lane = threadIdx.x & 31;
    int nw = (gridDim.x * blockDim.x) >> 5;
    float acc = 0.f;
    for (int c = gw; c < Nn; c += nw) {
        int beg = g_off[c], end = g_off[c + 1];
        float sc0 = s[(size_t)c*KK + lane];
        float sc1 = s[(size_t)c*KK + lane + 32];
        for (int j0 = beg; j0 < end; j0 += 32) {
            int jj = j0 + lane;
            int r = (jj < end) ? g_rows[jj] : 0;
            int cnt = min(32, end - j0);
            for (int k = 0; k < cnt; k++) {
                int rk = __shfl_sync(0xFFFFFFFFu, r, k);
                const float* sr = s + (size_t)rk * KK;
                acc += sr[lane] * sc0 + sr[lane + 32] * sc1;
            }
        }
    }
    #pragma unroll
    for (int o = 16; o; o >>= 1) acc += __shfl_xor_sync(0xFFFFFFFFu, acc, o);
    if (lane == 0) atomicAdd(&g_trace, (double)acc);
}

// ---------------- final scalar loss ----------------
__global__ __launch_bounds__(256) void k_final(float* __restrict__ out, int E, int out_size) {
    __shared__ float red[256];
    int t = threadIdx.x;

    float v = 0.f;
    for (int i = t; i < KK; i += 256) v += g_ca[i] * g_ca[i];
    red[t] = v; __syncthreads();
    for (int o = 128; o; o >>= 1) { if (t < o) red[t] += red[t + o]; __syncthreads(); }
    float ca2 = red[0]; __syncthreads();

    v = 0.f;
    for (int i = t; i < KK*KK; i += 256) v += g_ss[i] * g_ss[i];
    red[t] = v; __syncthreads();
    for (int o = 128; o; o >>= 1) { if (t < o) red[t] += red[t + o]; __syncthreads(); }
    float ss2 = red[0]; __syncthreads();

    v = 0.f;
    for (int i = t; i < KK; i += 256) v += g_ss[i*KK + i];
    red[t] = v; __syncthreads();
    for (int o = 128; o; o >>= 1) { if (t < o) red[t] += red[t + o]; __syncthreads(); }
    float trss = red[0]; __syncthreads();

    v = 0.f;
    for (int i = t; i < KK; i += 256) v += g_cs[i] * g_cs[i];
    red[t] = v; __syncthreads();
    for (int o = 128; o; o >>= 1) { if (t < o) red[t] += red[t + o]; __syncthreads(); }
    float cs2 = red[0]; __syncthreads();

    if (t == 0) {
        float two_m = (float)E;
        float tr_out = (float)g_trace;
        float spectral = -(tr_out - ca2 / two_m) / two_m;
        float ssfro = sqrtf(ss2);
        float ortho = sqrtf(fmaxf(2.0f - trss / (4.0f * ssfro), 0.0f));
        float cluster = sqrtf(cs2) / (float)Nn * 8.0f - 1.0f;
        float loss = spectral + ortho + cluster;
        for (int i = Nn*KK; i < out_size; i++) out[i] = loss;
    }
}

// ---------------- launch ----------------
extern "C" void kernel_launch(void* const* d_in, const int* in_sizes, int n_in,
                              void* d_out, int out_size) {
    const float* x   = (const float*)d_in[0];
    const int*   ei  = (const int*)d_in[1];
    const float* ew  = (const float*)d_in[2];
    const float* W1  = (const float*)d_in[3];
    const float* b1  = (const float*)d_in[4];
    const float* Wm1 = (const float*)d_in[5];
    const float* bm1 = (const float*)d_in[6];
    const float* Wm2 = (const float*)d_in[7];
    const float* bm2 = (const float*)d_in[8];
    float* out = (float*)d_out;
    int E = in_sizes[2];

    k_init<<<256, 256>>>();
    k_xw<<<512, 256>>>(x, W1);
    k_deg<<<512, 256>>>(ei, ew, E);
    k_dis<<<(Nn + 255) / 256, 256>>>();
    k_scan<<<1, 1024>>>();
    k_fill<<<512, 256>>>(ei, ew, E);
    k_gather<<<2048, 256>>>(b1);
    k_mlp<<<256, 256>>>(Wm1, bm1, Wm2, bm2, out);
    k_ss<<<256, 256>>>(out);
    k_trace<<<1024, 256>>>(out);
    k_final<<<1, 256>>>(out, E, out_size);
}

// round 3
// speedup vs baseline: 1.0125x; 1.0125x over previous
#include <cuda_runtime.h>

#define Nn 16384
#define EE 524288
#define CIN 128
#define HH 64
#define KK 64
#define NT 1024

// ---------------- device scratch ----------------
__device__ float g_xw[Nn*HH];                // x @ W1
__device__ float g_h[Nn*HH];                 // relu'd GCN output
__device__ float g_dis[Nn];                  // rsqrt(deg)
__device__ int   g_cnt[Nn];                  // in-edge counts (column sums of adj)
__device__ int   g_off[Nn+1];                // CSC offsets
__device__ int   g_cur[Nn];                  // fill cursors
__device__ unsigned long long g_ed[EE];      // packed (w_bits<<32 | row)
__device__ float g_ss[KK*KK];
__device__ float g_ca[KK];
__device__ float g_cs[KK];
__device__ double g_trace;
__device__ unsigned g_bar_cnt;               // persistent barrier state (wrap-safe)
__device__ unsigned g_bar_gen;

// grid-wide barrier: all gridDim.x blocks must be co-resident (1 block/SM)
__device__ __forceinline__ void gsync() {
    __syncthreads();
    if (threadIdx.x == 0) {
        volatile unsigned* genp = &g_bar_gen;
        unsigned gen = *genp;
        __threadfence();
        if (atomicAdd(&g_bar_cnt, 1u) == gridDim.x - 1) {
            g_bar_cnt = 0;
            __threadfence();
            atomicAdd(&g_bar_gen, 1u);
        } else {
            while (*genp == gen) __nanosleep(64);
        }
        __threadfence();
    }
    __syncthreads();
}

__global__ void __launch_bounds__(NT, 1)
mega(const float* __restrict__ x, const int* __restrict__ ei,
     const float* __restrict__ ew,
     const float* __restrict__ W1, const float* __restrict__ b1,
     const float* __restrict__ Wm1, const float* __restrict__ bm1,
     const float* __restrict__ Wm2, const float* __restrict__ bm2,
     float* __restrict__ out, int E, int out_size)
{
    __shared__ float shbuf[12288];   // 48 KB, re-carved per phase
    const int tid = threadIdx.x, bid = blockIdx.x;
    const int nth = gridDim.x * NT;
    const int gt = bid * NT + tid;
    const int lane = tid & 31, wid = tid >> 5;
    const int gwarp = bid * 32 + wid;
    const int nwarp = gridDim.x * 32;

    // ================= P0: zero accumulators + xw = x @ W1 =================
    for (int j = gt; j < Nn; j += nth) g_cnt[j] = 0;
    for (int j = gt; j < KK*KK; j += nth) g_ss[j] = 0.f;
    if (gt < KK) { g_ca[gt] = 0.f; g_cs[gt] = 0.f; }
    if (gt == 0) g_trace = 0.0;

    for (int j = tid; j < CIN*HH; j += NT) shbuf[j] = W1[j];
    __syncthreads();
    for (int r0 = gwarp * 4; r0 < Nn; r0 += nwarp * 4) {
        float a00=0,a01=0,a10=0,a11=0,a20=0,a21=0,a30=0,a31=0;
        const float* x0 = x + (size_t)r0 * CIN;
        #pragma unroll 4
        for (int k = 0; k < CIN; k++) {
            float w0 = shbuf[k*HH + lane], w1 = shbuf[k*HH + lane + 32];
            float x_0 = __ldg(x0 + k);
            float x_1 = __ldg(x0 + CIN + k);
            float x_2 = __ldg(x0 + 2*CIN + k);
            float x_3 = __ldg(x0 + 3*CIN + k);
            a00 += x_0*w0; a01 += x_0*w1;
            a10 += x_1*w0; a11 += x_1*w1;
            a20 += x_2*w0; a21 += x_2*w1;
            a30 += x_3*w0; a31 += x_3*w1;
        }
        float* o = g_xw + (size_t)r0 * HH;
        o[lane] = a00;        o[lane+32] = a01;
        o[HH+lane] = a10;     o[HH+lane+32] = a11;
        o[2*HH+lane] = a20;   o[2*HH+lane+32] = a21;
        o[3*HH+lane] = a30;   o[3*HH+lane+32] = a31;
    }
    gsync();

    // ================= P1: count in-edges per column =================
    for (int e = gt; e < E; e += nth) atomicAdd(&g_cnt[ei[E + e]], 1);
    gsync();

    // ================= P2: exclusive scan (block 0 only) =================
    if (bid == 0) {
        int* wsum = (int*)shbuf;
        int base = tid * 16;
        int local[16];
        int s = 0;
        #pragma unroll
        for (int i = 0; i < 16; i++) { local[i] = g_cnt[base + i]; s += local[i]; }
        int ws = s;
        #pragma unroll
        for (int o = 1; o < 32; o <<= 1) {
            int v = __shfl_up_sync(0xFFFFFFFFu, ws, o);
            if (lane >= o) ws += v;
        }
        if (lane == 31) wsum[wid] = ws;
        __syncthreads();
        if (tid < 32) {
            int v = wsum[tid];
            #pragma unroll
            for (int o = 1; o < 32; o <<= 1) {
                int u = __shfl_up_sync(0xFFFFFFFFu, v, o);
                if (tid >= o) v += u;
            }
            wsum[tid] = v;
        }
        __syncthreads();
        int run = (wid ? wsum[wid - 1] : 0) + ws - s;
        #pragma unroll
        for (int i = 0; i < 16; i++) {
            g_off[base + i] = run;
            g_cur[base + i] = run;
            run += local[i];
        }
        if (tid == NT - 1) g_off[Nn] = run;
    }
    gsync();

    // ================= P3: fill buckets with packed (w, row) =================
    for (int e = gt; e < E; e += nth) {
        int r = __ldg(ei + e);
        int c = __ldg(ei + E + e);
        float w = __ldg(ew + e);
        int pos = atomicAdd(&g_cur[c], 1);
        g_ed[pos] = ((unsigned long long)__float_as_uint(w) << 32) | (unsigned)r;
    }
    gsync();

    // ================= P4: deg + dis from buckets (no atomics) =================
    for (int c = gwarp; c < Nn; c += nwarp) {
        int beg = g_off[c], end = g_off[c + 1];
        float s = 0.f;
        for (int j = beg + lane; j < end; j += 32)
            s += __uint_as_float((unsigned)(g_ed[j] >> 32));
        #pragma unroll
        for (int o = 16; o; o >>= 1) s += __shfl_xor_sync(0xFFFFFFFFu, s, o);
        if (lane == 0) g_dis[c] = rsqrtf(s + 1.0f);   // +1 self loop; always > 0
    }
    gsync();

    // ================= P5: gather + self loop + bias + relu =================
    {
        const float2* xw2 = (const float2*)g_xw;
        float2* h2 = (float2*)g_h;
        float bb0 = b1[2*lane], bb1 = b1[2*lane + 1];
        for (int c = gwarp; c < Nn; c += nwarp) {
            int beg = g_off[c], end = g_off[c + 1];
            float dc = g_dis[c];
            float2 self = xw2[c*32 + lane];
            float a0 = self.x * dc * dc, a1 = self.y * dc * dc;
            for (int j0 = beg; j0 < end; j0 += 32) {
                int jj = j0 + lane;
                int r = 0; float wn = 0.f;
                if (jj < end) {
                    unsigned long long p = g_ed[jj];
                    r = (int)(unsigned)(p & 0xFFFFFFFFull);
                    wn = __uint_as_float((unsigned)(p >> 32)) * g_dis[r] * dc;
                }
                int cnt = min(32, end - j0);
                for (int k = 0; k < cnt; k++) {
                    int rk = __shfl_sync(0xFFFFFFFFu, r, k);
                    float wk = __shfl_sync(0xFFFFFFFFu, wn, k);
                    float2 v = xw2[rk*32 + lane];
                    a0 += v.x * wk; a1 += v.y * wk;
                }
            }
            float2 o;
            o.x = fmaxf(a0 + bb0, 0.f);
            o.y = fmaxf(a1 + bb1, 0.f);
            h2[c*32 + lane] = o;
        }
    }
    gsync();

    // ================= P6: MLP + softmax + cs/ca =================
    {
        float* W1s = shbuf;
        float* W2s = shbuf + 4096;
        float* tb  = shbuf + 8192 + wid * HH;
        for (int j = tid; j < HH*HH; j += NT) W1s[j] = Wm1[j];
        for (int j = tid; j < HH*KK; j += NT) W2s[j] = Wm2[j];
        __syncthreads();
        float b1a = bm1[lane], b1b = bm1[lane + 32];
        float b2a = bm2[lane], b2b = bm2[lane + 32];
        float cs0 = 0.f, cs1 = 0.f, ca0 = 0.f, ca1 = 0.f;
        for (int row = gwarp; row < Nn; row += nwarp) {
            const float* hrow = g_h + (size_t)row * HH;
            float t0 = b1a, t1 = b1b;
            #pragma unroll 8
            for (int k = 0; k < HH; k++) {
                float hk = hrow[k];
                t0 += hk * W1s[k*HH + lane];
                t1 += hk * W1s[k*HH + lane + 32];
            }
            tb[lane] = t0; tb[lane + 32] = t1;
            __syncwarp();
            float l0 = b2a, l1 = b2b;
            #pragma unroll 8
            for (int k = 0; k < HH; k++) {
                float tk = tb[k];
                l0 += tk * W2s[k*KK + lane];
                l1 += tk * W2s[k*KK + lane + 32];
            }
            __syncwarp();
            float mx = fmaxf(l0, l1);
            #pragma unroll
            for (int o = 16; o; o >>= 1) mx = fmaxf(mx, __shfl_xor_sync(0xFFFFFFFFu, mx, o));
            float e0 = __expf(l0 - mx), e1 = __expf(l1 - mx);
            float sm = e0 + e1;
            #pragma unroll
            for (int o = 16; o; o >>= 1) sm += __shfl_xor_sync(0xFFFFFFFFu, sm, o);
            float inv = 1.0f / sm;
            float s0 = e0 * inv, s1 = e1 * inv;
            out[(size_t)row*KK + lane]      = s0;
            out[(size_t)row*KK + lane + 32] = s1;
            cs0 += s0; cs1 += s1;
            float da = (float)g_cnt[row];
            ca0 += s0 * da; ca1 += s1 * da;
        }
        atomicAdd(&g_cs[lane], cs0); atomicAdd(&g_cs[lane + 32], cs1);
        atomicAdd(&g_ca[lane], ca0); atomicAdd(&g_ca[lane + 32], ca1);
    }
    gsync();

    // ================= P7: ss = s^T s  AND  trace(s^T adj s) =================
    {
        // --- ss: block-stride rows, 1024 threads, 4 accs each ---
        float* srow = shbuf + 10240;
        int a = tid >> 4;             // 0..63
        int b0 = tid & 15;            // float4 index 0..15
        float ac0=0, ac1=0, ac2=0, ac3=0;
        for (int row = bid; row < Nn; row += gridDim.x) {
            if (tid < 16) ((float4*)srow)[tid] = ((const float4*)(out + (size_t)row*KK))[tid];
            __syncthreads();
            float sa = srow[a];
            float4 vb = ((const float4*)srow)[b0];
            ac0 += sa * vb.x; ac1 += sa * vb.y; ac2 += sa * vb.z; ac3 += sa * vb.w;
            __syncthreads();
        }
        atomicAdd(&g_ss[a*KK + b0*4 + 0], ac0);
        atomicAdd(&g_ss[a*KK + b0*4 + 1], ac1);
        atomicAdd(&g_ss[a*KK + b0*4 + 2], ac2);
        atomicAdd(&g_ss[a*KK + b0*4 + 3], ac3);

        // --- trace via buckets: warp per node ---
        const float2* s2 = (const float2*)out;
        float tacc = 0.f;
        for (int c = gwarp; c < Nn; c += nwarp) {
            int beg = g_off[c], end = g_off[c + 1];
            float2 sc = s2[c*32 + lane];
            for (int j0 = beg; j0 < end; j0 += 32) {
                int jj = j0 + lane;
                int r = (jj < end) ? (int)(unsigned)(g_ed[jj] & 0xFFFFFFFFull) : 0;
                int cnt = min(32, end - j0);
                for (int k = 0; k < cnt; k++) {
                    int rk = __shfl_sync(0xFFFFFFFFu, r, k);
                    float2 v = s2[rk*32 + lane];
                    tacc += v.x * sc.x + v.y * sc.y;
                }
            }
        }
        #pragma unroll
        for (int o = 16; o; o >>= 1) tacc += __shfl_xor_sync(0xFFFFFFFFu, tacc, o);
        if (lane == 0) atomicAdd(&g_trace, (double)tacc);
    }
    gsync();

    // ================= P8: final loss (block 0) =================
    if (bid == 0) {
        float* red = shbuf;
        float v;

        v = 0.f;
        for (int i = tid; i < KK; i += NT) v += g_ca[i] * g_ca[i];
        red[tid] = v; __syncthreads();
        for (int o = NT/2; o; o >>= 1) { if (tid < o) red[tid] += red[tid + o]; __syncthreads(); }
        float ca2 = red[0]; __syncthreads();

        v = 0.f;
        for (int i = tid; i < KK*KK; i += NT) { float u = g_ss[i]; v += u * u; }
        red[tid] = v; __syncthreads();
        for (int o = NT/2; o; o >>= 1) { if (tid < o) red[tid] += red[tid + o]; __syncthreads(); }
        float ss2 = red[0]; __syncthreads();

        v = 0.f;
        for (int i = tid; i < KK; i += NT) v += g_ss[i*KK + i];
        red[tid] = v; __syncthreads();
        for (int o = NT/2; o; o >>= 1) { if (tid < o) red[tid] += red[tid + o]; __syncthreads(); }
        float trss = red[0]; __syncthreads();

        v = 0.f;
        for (int i = tid; i < KK; i += NT) v += g_cs[i] * g_cs[i];
        red[tid] = v; __syncthreads();
        for (int o = NT/2; o; o >>= 1) { if (tid < o) red[tid] += red[tid + o]; __syncthreads(); }
        float cs2 = red[0]; __syncthreads();

        if (tid == 0) {
            float two_m = (float)E;
            float tr_out = (float)g_trace;
            float spectral = -(tr_out - ca2 / two_m) / two_m;
            float ssfro = sqrtf(ss2);
            float ortho = sqrtf(fmaxf(2.0f - trss / (4.0f * ssfro), 0.0f));
            float cluster = sqrtf(cs2) / (float)Nn * 8.0f - 1.0f;
            float loss = spectral + ortho + cluster;
            for (int i = Nn*KK; i < out_size; i++) out[i] = loss;
        }
    }
}

// ---------------- launch ----------------
extern "C" void kernel_launch(void* const* d_in, const int* in_sizes, int n_in,
                              void* d_out, int out_size) {
    const float* x   = (const float*)d_in[0];
    const int*   ei  = (const int*)d_in[1];
    const float* ew  = (const float*)d_in[2];
    const float* W1  = (const float*)d_in[3];
    const float* b1  = (const float*)d_in[4];
    const float* Wm1 = (const float*)d_in[5];
    const float* bm1 = (const float*)d_in[6];
    const float* Wm2 = (const float*)d_in[7];
    const float* bm2 = (const float*)d_in[8];
    float* out = (float*)d_out;
    int E = in_sizes[2];

    int nsm = 148;
    cudaDeviceGetAttribute(&nsm, cudaDevAttrMultiProcessorCount, 0);
    if (nsm < 1) nsm = 148;
    if (nsm > 512) nsm = 512;

    mega<<<nsm, NT>>>(x, ei, ew, W1, b1, Wm1, bm1, Wm2, bm2, out, E, out_size);
}

// round 4
// speedup vs baseline: 1.2292x; 1.2140x over previous
#include <cuda_runtime.h>

#define Nn 16384
#define EE 524288
#define CIN 128
#define HH 64
#define KK 64
#define NT 1024

// ---------------- device scratch ----------------
__device__ float g_xw[Nn*HH];
__device__ float g_h[Nn*HH];
__device__ float g_dis[Nn];
__device__ float g_deg[Nn];
__device__ int   g_cnt[Nn];
__device__ int   g_off[Nn+1];
__device__ int   g_cur[Nn];
__device__ unsigned long long g_ed[EE];   // (wn_bits<<32) | row
__device__ float g_W[HH*KK];              // collapsed Wm1@Wm2, [k][c]
__device__ float g_bb[KK];                // collapsed bias
__device__ float g_ss[KK*KK];
__device__ float g_ca[KK];
__device__ float g_cs[KK];
__device__ double g_trace;
__device__ unsigned g_bar_cnt, g_bar_gen;

__device__ __forceinline__ void gsync() {
    __syncthreads();
    if (threadIdx.x == 0) {
        volatile unsigned* genp = &g_bar_gen;
        unsigned gen = *genp;
        __threadfence();
        if (atomicAdd(&g_bar_cnt, 1u) == gridDim.x - 1) {
            g_bar_cnt = 0;
            __threadfence();
            atomicAdd(&g_bar_gen, 1u);
        } else {
            while (*genp == gen) __nanosleep(32);
        }
        __threadfence();
    }
    __syncthreads();
}

__global__ void __launch_bounds__(NT, 1)
mega(const float* __restrict__ x, const int* __restrict__ ei,
     const float* __restrict__ ew,
     const float* __restrict__ W1, const float* __restrict__ b1,
     const float* __restrict__ Wm1, const float* __restrict__ bm1,
     const float* __restrict__ Wm2, const float* __restrict__ bm2,
     float* __restrict__ out, int E, int out_size)
{
    __shared__ float shbuf[8192];     // 32 KB, re-carved per phase
    __shared__ float tr_part;
    const int tid = threadIdx.x, bid = blockIdx.x;
    const int nth = gridDim.x * NT;
    const int gt = bid * NT + tid;
    const int lane = tid & 31, wid = tid >> 5;
    const int gwarp = bid * 32 + wid;
    const int nwarp = gridDim.x * 32;
    const int l16 = lane & 15;
    const int ghalf = gwarp * 2 + (lane >> 4);
    const int nhalf = nwarp * 2;

    // ============ PA: zero accumulators ============
    for (int j = gt; j < Nn; j += nth) { g_cnt[j] = 0; g_deg[j] = 1.0f; }
    for (int j = gt; j < KK*KK; j += nth) g_ss[j] = 0.f;
    if (gt < KK) { g_ca[gt] = 0.f; g_cs[gt] = 0.f; }
    if (gt == 0) g_trace = 0.0;
    gsync();

    // ============ PB: edge atomics + W-collapse + xw GEMM ============
    for (int j = tid; j < CIN*HH; j += NT) shbuf[j] = W1[j];

    for (int e = gt; e < E; e += nth) {
        int c = __ldg(ei + E + e);
        atomicAdd(&g_deg[c], __ldg(ew + e));
        atomicAdd(&g_cnt[c], 1);
    }

    if (bid == 0) {
        // g_W[k][c] = sum_j Wm1[k][j] * Wm2[j][c]
        int a = tid >> 4;
        int c0 = (tid & 15) * 4;
        float4 acc = make_float4(0.f, 0.f, 0.f, 0.f);
        for (int j = 0; j < HH; j++) {
            float m = __ldg(Wm1 + a*HH + j);
            float4 w2 = __ldg((const float4*)(Wm2 + j*KK + c0));
            acc.x += m * w2.x; acc.y += m * w2.y;
            acc.z += m * w2.z; acc.w += m * w2.w;
        }
        ((float4*)g_W)[tid] = acc;
        if (tid < KK) {
            float b = __ldg(bm2 + tid);
            for (int j = 0; j < HH; j++) b += __ldg(bm1 + j) * __ldg(Wm2 + j*KK + tid);
            g_bb[tid] = b;
        }
    }

    __syncthreads();
    for (int r0 = gwarp * 4; r0 < Nn; r0 += nwarp * 4) {
        float a00=0,a01=0,a10=0,a11=0,a20=0,a21=0,a30=0,a31=0;
        const float* x0 = x + (size_t)r0 * CIN;
        #pragma unroll 4
        for (int k = 0; k < CIN; k++) {
            float w0 = shbuf[k*HH + lane], w1 = shbuf[k*HH + lane + 32];
            float x_0 = __ldg(x0 + k);
            float x_1 = __ldg(x0 + CIN + k);
            float x_2 = __ldg(x0 + 2*CIN + k);
            float x_3 = __ldg(x0 + 3*CIN + k);
            a00 += x_0*w0; a01 += x_0*w1;
            a10 += x_1*w0; a11 += x_1*w1;
            a20 += x_2*w0; a21 += x_2*w1;
            a30 += x_3*w0; a31 += x_3*w1;
        }
        float* o = g_xw + (size_t)r0 * HH;
        o[lane] = a00;        o[lane+32] = a01;
        o[HH+lane] = a10;     o[HH+lane+32] = a11;
        o[2*HH+lane] = a20;   o[2*HH+lane+32] = a21;
        o[3*HH+lane] = a30;   o[3*HH+lane+32] = a31;
    }
    gsync();

    // ============ PC: block0 scan || others dis ============
    if (bid == 0) {
        int* wsum = (int*)shbuf;
        int base = tid * 16;
        int local[16];
        int s = 0;
        #pragma unroll
        for (int i = 0; i < 16; i++) { local[i] = g_cnt[base + i]; s += local[i]; }
        int ws = s;
        #pragma unroll
        for (int o = 1; o < 32; o <<= 1) {
            int v = __shfl_up_sync(0xFFFFFFFFu, ws, o);
            if (lane >= o) ws += v;
        }
        if (lane == 31) wsum[wid] = ws;
        __syncthreads();
        if (tid < 32) {
            int v = wsum[tid];
            #pragma unroll
            for (int o = 1; o < 32; o <<= 1) {
                int u = __shfl_up_sync(0xFFFFFFFFu, v, o);
                if (tid >= o) v += u;
            }
            wsum[tid] = v;
        }
        __syncthreads();
        int run = (wid ? wsum[wid - 1] : 0) + ws - s;
        #pragma unroll
        for (int i = 0; i < 16; i++) {
            g_off[base + i] = run;
            g_cur[base + i] = run;
            run += local[i];
        }
        if (tid == NT - 1) g_off[Nn] = run;
    } else {
        for (int j = (bid - 1) * NT + tid; j < Nn; j += (gridDim.x - 1) * NT)
            g_dis[j] = rsqrtf(g_deg[j]);
    }
    gsync();

    // ============ PD: fill buckets with normalized weight ============
    for (int e = gt; e < E; e += nth) {
        int r = __ldg(ei + e);
        int c = __ldg(ei + E + e);
        float wn = g_dis[r] * __ldg(ew + e) * g_dis[c];
        int pos = atomicAdd(&g_cur[c], 1);
        g_ed[pos] = ((unsigned long long)__float_as_uint(wn) << 32) | (unsigned)r;
    }
    gsync();

    // ============ PE: gather + self loop + bias + relu ============
    {
        const float4* xw4 = (const float4*)g_xw;
        float4* h4 = (float4*)g_h;
        float4 bb = __ldg((const float4*)b1 + l16);
        for (int c = ghalf; c < Nn; c += nhalf) {
            int beg = g_off[c], end = g_off[c + 1];
            float dc = g_dis[c];
            float sw = dc * dc;
            float4 acc = xw4[c*16 + l16];
            acc.x *= sw; acc.y *= sw; acc.z *= sw; acc.w *= sw;
            int j = beg;
            for (; j + 4 <= end; j += 4) {
                unsigned long long p0 = __ldg(g_ed + j);
                unsigned long long p1 = __ldg(g_ed + j + 1);
                unsigned long long p2 = __ldg(g_ed + j + 2);
                unsigned long long p3 = __ldg(g_ed + j + 3);
                int r0 = (int)(unsigned)p0, r1 = (int)(unsigned)p1;
                int r2 = (int)(unsigned)p2, r3 = (int)(unsigned)p3;
                float w0 = __uint_as_float((unsigned)(p0 >> 32));
                float w1 = __uint_as_float((unsigned)(p1 >> 32));
                float w2 = __uint_as_float((unsigned)(p2 >> 32));
                float w3 = __uint_as_float((unsigned)(p3 >> 32));
                float4 v0 = xw4[r0*16 + l16];
                float4 v1 = xw4[r1*16 + l16];
                float4 v2 = xw4[r2*16 + l16];
                float4 v3 = xw4[r3*16 + l16];
                acc.x += w0*v0.x + w1*v1.x + w2*v2.x + w3*v3.x;
                acc.y += w0*v0.y + w1*v1.y + w2*v2.y + w3*v3.y;
                acc.z += w0*v0.z + w1*v1.z + w2*v2.z + w3*v3.z;
                acc.w += w0*v0.w + w1*v1.w + w2*v2.w + w3*v3.w;
            }
            for (; j < end; j++) {
                unsigned long long p = __ldg(g_ed + j);
                int r = (int)(unsigned)p;
                float w = __uint_as_float((unsigned)(p >> 32));
                float4 v = xw4[r*16 + l16];
                acc.x += w*v.x; acc.y += w*v.y; acc.z += w*v.z; acc.w += w*v.w;
            }
            acc.x = fmaxf(acc.x + bb.x, 0.f);
            acc.y = fmaxf(acc.y + bb.y, 0.f);
            acc.z = fmaxf(acc.z + bb.z, 0.f);
            acc.w = fmaxf(acc.w + bb.w, 0.f);
            h4[c*16 + l16] = acc;
        }
    }
    gsync();

    // ============ PF: collapsed MLP + softmax + cs/ca ============
    {
        float* Ws = shbuf;   // 4096 floats
        for (int j = tid; j < HH*KK; j += NT) Ws[j] = g_W[j];
        __syncthreads();
        float b2a = g_bb[lane], b2b = g_bb[lane + 32];
        float cs0 = 0.f, cs1 = 0.f, ca0 = 0.f, ca1 = 0.f;
        for (int row = gwarp; row < Nn; row += nwarp) {
            const float* hrow = g_h + (size_t)row * HH;
            float l0 = b2a, l1 = b2b;
            #pragma unroll 8
            for (int k = 0; k < HH; k++) {
                float hk = __ldg(hrow + k);
                l0 += hk * Ws[k*KK + lane];
                l1 += hk * Ws[k*KK + lane + 32];
            }
            float mx = fmaxf(l0, l1);
            #pragma unroll
            for (int o = 16; o; o >>= 1) mx = fmaxf(mx, __shfl_xor_sync(0xFFFFFFFFu, mx, o));
            float e0 = __expf(l0 - mx), e1 = __expf(l1 - mx);
            float sm = e0 + e1;
            #pragma unroll
            for (int o = 16; o; o >>= 1) sm += __shfl_xor_sync(0xFFFFFFFFu, sm, o);
            float inv = 1.0f / sm;
            float s0 = e0 * inv, s1 = e1 * inv;
            out[(size_t)row*KK + lane]      = s0;
            out[(size_t)row*KK + lane + 32] = s1;
            cs0 += s0; cs1 += s1;
            float da = (float)g_cnt[row];
            ca0 += s0 * da; ca1 += s1 * da;
        }
        atomicAdd(&g_cs[lane], cs0); atomicAdd(&g_cs[lane + 32], cs1);
        atomicAdd(&g_ca[lane], ca0); atomicAdd(&g_ca[lane + 32], ca1);
    }
    gsync();

    // ============ PG: ss = s^T s AND trace(s^T A s) ============
    {
        if (tid == 0) tr_part = 0.f;
        // --- ss: 16 rows per block-chunk ---
        float* srows = shbuf;  // 1024 floats
        int a = tid >> 4, q = tid & 15;
        float ac0=0, ac1=0, ac2=0, ac3=0;
        for (int base = bid * 16; base < Nn; base += gridDim.x * 16) {
            __syncthreads();
            if (tid < 256) ((float4*)srows)[tid] = ((const float4*)(out + (size_t)base*KK))[tid];
            __syncthreads();
            #pragma unroll
            for (int r = 0; r < 16; r++) {
                float sa = srows[r*KK + a];
                float4 vb = ((const float4*)(srows + r*KK))[q];
                ac0 += sa * vb.x; ac1 += sa * vb.y;
                ac2 += sa * vb.z; ac3 += sa * vb.w;
            }
        }
        atomicAdd(&g_ss[a*KK + q*4 + 0], ac0);
        atomicAdd(&g_ss[a*KK + q*4 + 1], ac1);
        atomicAdd(&g_ss[a*KK + q*4 + 2], ac2);
        atomicAdd(&g_ss[a*KK + q*4 + 3], ac3);
        __syncthreads();

        // --- trace via buckets: 16 lanes per node, unroll 4 ---
        const float4* s4 = (const float4*)out;
        float tacc = 0.f;
        for (int c = ghalf; c < Nn; c += nhalf) {
            int beg = g_off[c], end = g_off[c + 1];
            float4 sc = s4[c*16 + l16];
            int j = beg;
            for (; j + 4 <= end; j += 4) {
                int r0 = (int)(unsigned)__ldg(g_ed + j);
                int r1 = (int)(unsigned)__ldg(g_ed + j + 1);
                int r2 = (int)(unsigned)__ldg(g_ed + j + 2);
                int r3 = (int)(unsigned)__ldg(g_ed + j + 3);
                float4 v0 = s4[r0*16 + l16];
                float4 v1 = s4[r1*16 + l16];
                float4 v2 = s4[r2*16 + l16];
                float4 v3 = s4[r3*16 + l16];
                tacc += (v0.x + v1.x + v2.x + v3.x) * 0.f; // placeholder removed below
                tacc += v0.x*sc.x + v0.y*sc.y + v0.z*sc.z + v0.w*sc.w;
                tacc += v1.x*sc.x + v1.y*sc.y + v1.z*sc.z + v1.w*sc.w;
                tacc += v2.x*sc.x + v2.y*sc.y + v2.z*sc.z + v2.w*sc.w;
                tacc += v3.x*sc.x + v3.y*sc.y + v3.z*sc.z + v3.w*sc.w;
            }
            for (; j < end; j++) {
                int r = (int)(unsigned)__ldg(g_ed + j);
                float4 v = s4[r*16 + l16];
                tacc += v.x*sc.x + v.y*sc.y + v.z*sc.z + v.w*sc.w;
            }
        }
        #pragma unroll
        for (int o = 16; o; o >>= 1) tacc += __shfl_xor_sync(0xFFFFFFFFu, tacc, o);
        if (lane == 0) atomicAdd(&tr_part, tacc);
        __syncthreads();
        if (tid == 0) atomicAdd(&g_trace, (double)tr_part);
    }
    gsync();

    // ============ PH: final loss (block 0) ============
    if (bid == 0) {
        float* red = shbuf;
        float v;

        v = 0.f;
        for (int i = tid; i < KK; i += NT) v += g_ca[i] * g_ca[i];
        red[tid] = v; __syncthreads();
        for (int o = NT/2; o; o >>= 1) { if (tid < o) red[tid] += red[tid + o]; __syncthreads(); }
        float ca2 = red[0]; __syncthreads();

        v = 0.f;
        for (int i = tid; i < KK*KK; i += NT) { float u = g_ss[i]; v += u * u; }
        red[tid] = v; __syncthreads();
        for (int o = NT/2; o; o >>= 1) { if (tid < o) red[tid] += red[tid + o]; __syncthreads(); }
        float ss2 = red[0]; __syncthreads();

        v = 0.f;
        for (int i = tid; i < KK; i += NT) v += g_ss[i*KK + i];
        red[tid] = v; __syncthreads();
        for (int o = NT/2; o; o >>= 1) { if (tid < o) red[tid] += red[tid + o]; __syncthreads(); }
        float trss = red[0]; __syncthreads();

        v = 0.f;
        for (int i = tid; i < KK; i += NT) v += g_cs[i] * g_cs[i];
        red[tid] = v; __syncthreads();
        for (int o = NT/2; o; o >>= 1) { if (tid < o) red[tid] += red[tid + o]; __syncthreads(); }
        float cs2 = red[0]; __syncthreads();

        if (tid == 0) {
            float two_m = (float)E;
            float tr_out = (float)g_trace;
            float spectral = -(tr_out - ca2 / two_m) / two_m;
            float ssfro = sqrtf(ss2);
            float ortho = sqrtf(fmaxf(2.0f - trss / (4.0f * ssfro), 0.0f));
            float cluster = sqrtf(cs2) / (float)Nn * 8.0f - 1.0f;
            float loss = spectral + ortho + cluster;
            for (int i = Nn*KK; i < out_size; i++) out[i] = loss;
        }
    }
}

// ---------------- launch ----------------
extern "C" void kernel_launch(void* const* d_in, const int* in_sizes, int n_in,
                              void* d_out, int out_size) {
    const float* x   = (const float*)d_in[0];
    const int*   ei  = (const int*)d_in[1];
    const float* ew  = (const float*)d_in[2];
    const float* W1  = (const float*)d_in[3];
    const float* b1  = (const float*)d_in[4];
    const float* Wm1 = (const float*)d_in[5];
    const float* bm1 = (const float*)d_in[6];
    const float* Wm2 = (const float*)d_in[7];
    const float* bm2 = (const float*)d_in[8];
    float* out = (float*)d_out;
    int E = in_sizes[2];

    int nsm = 148;
    cudaDeviceGetAttribute(&nsm, cudaDevAttrMultiProcessorCount, 0);
    if (nsm < 2) nsm = 148;
    if (nsm > 512) nsm = 512;

    mega<<<nsm, NT>>>(x, ei, ew, W1, b1, Wm1, bm1, Wm2, bm2, out, E, out_size);
}

// round 5
// speedup vs baseline: 1.2436x; 1.0117x over previous
#include <cuda_runtime.h>

#define Nn 16384
#define EE 524288
#define CIN 128
#define HH 64
#define KK 64
#define NT 1024

// ---------------- device scratch ----------------
__device__ float g_xw[Nn*HH];
__device__ float g_h[Nn*HH];
__device__ float g_dis[Nn];
__device__ float g_deg[Nn];
__device__ int   g_cnt[Nn];
__device__ int   g_off[Nn+1];
__device__ int   g_cur[Nn];
__device__ unsigned long long g_ed[EE];   // (wn_bits<<32) | row
__device__ float g_W[HH*KK];              // collapsed Wm1@Wm2, [k][c]
__device__ float g_bb[KK];                // collapsed bias
__device__ float g_ss[KK*KK];
__device__ float g_ca[KK];
__device__ float g_cs[KK];
__device__ double g_trace;
__device__ unsigned g_bar_cnt, g_bar_gen;
__device__ unsigned g_ws0, g_ws1;         // work-steal cursors

__device__ __forceinline__ void gsync() {
    __syncthreads();
    if (threadIdx.x == 0) {
        volatile unsigned* genp = &g_bar_gen;
        unsigned gen = *genp;
        __threadfence();
        if (atomicAdd(&g_bar_cnt, 1u) == gridDim.x - 1) {
            g_bar_cnt = 0;
            __threadfence();
            atomicAdd(&g_bar_gen, 1u);
        } else {
            while (*genp == gen) __nanosleep(32);
        }
        __threadfence();
    }
    __syncthreads();
}

__device__ __forceinline__ float dot4(float4 a, float4 b) {
    return a.x*b.x + a.y*b.y + a.z*b.z + a.w*b.w;
}

__global__ void __launch_bounds__(NT, 1)
mega(const float* __restrict__ x, const int* __restrict__ ei,
     const float* __restrict__ ew,
     const float* __restrict__ W1, const float* __restrict__ b1,
     const float* __restrict__ Wm1, const float* __restrict__ bm1,
     const float* __restrict__ Wm2, const float* __restrict__ bm2,
     float* __restrict__ out, int E, int out_size)
{
    __shared__ float shbuf[8704];   // 34 KB, re-carved per phase
    __shared__ float tr_part;
    const int tid = threadIdx.x, bid = blockIdx.x;
    const int nth = gridDim.x * NT;
    const int gt = bid * NT + tid;
    const int lane = tid & 31, wid = tid >> 5;
    const int gwarp = bid * 32 + wid;
    const int nwarp = gridDim.x * 32;
    const int l16 = lane & 15;
    const unsigned hmask = 0xFFFFu << (lane & 16);
    const int hsrc = lane & 16;

    // ============ PA: zero accumulators ============
    for (int j = gt; j < Nn; j += nth) { g_cnt[j] = 0; g_deg[j] = 1.0f; }
    for (int j = gt; j < KK*KK; j += nth) g_ss[j] = 0.f;
    if (gt < KK) { g_ca[gt] = 0.f; g_cs[gt] = 0.f; }
    if (gt == 0) { g_trace = 0.0; g_ws0 = 0u; g_ws1 = 0u; }
    gsync();

    // ============ PB: edge atomics + W-collapse + xw GEMM ============
    // stage W1 transposed: shbuf[c*132 + k] = W1[k*HH + c]
    for (int j = tid; j < CIN*HH; j += NT)
        shbuf[(j & 63) * 132 + (j >> 6)] = W1[j];

    for (int e = gt; e < E; e += nth) {
        int c = __ldg(ei + E + e);
        atomicAdd(&g_deg[c], __ldg(ew + e));
        atomicAdd(&g_cnt[c], 1);
    }

    if (bid == 0) {
        // g_W[k][c] = sum_j Wm1[k][j] * Wm2[j][c]
        int a = tid >> 4;
        int c0 = (tid & 15) * 4;
        float4 acc = make_float4(0.f, 0.f, 0.f, 0.f);
        for (int j = 0; j < HH; j++) {
            float m = __ldg(Wm1 + a*HH + j);
            float4 w2 = __ldg((const float4*)(Wm2 + j*KK + c0));
            acc.x += m * w2.x; acc.y += m * w2.y;
            acc.z += m * w2.z; acc.w += m * w2.w;
        }
        ((float4*)g_W)[tid] = acc;
        if (tid < KK) {
            float b = __ldg(bm2 + tid);
            for (int j = 0; j < HH; j++) b += __ldg(bm1 + j) * __ldg(Wm2 + j*KK + tid);
            g_bb[tid] = b;
        }
    }
    __syncthreads();

    {
        int r0 = gwarp * 4;
        if (r0 < Nn) {
            float a00=0,a01=0,a10=0,a11=0,a20=0,a21=0,a30=0,a31=0;
            const float* x0 = x + (size_t)r0 * CIN;
            const float* wp0 = shbuf + lane * 132;
            const float* wp1 = shbuf + (lane + 32) * 132;
            #pragma unroll 4
            for (int k = 0; k < CIN; k += 4) {
                float4 w0v = *(const float4*)(wp0 + k);
                float4 w1v = *(const float4*)(wp1 + k);
                float4 x0v = __ldg((const float4*)(x0 + k));
                float4 x1v = __ldg((const float4*)(x0 + CIN + k));
                float4 x2v = __ldg((const float4*)(x0 + 2*CIN + k));
                float4 x3v = __ldg((const float4*)(x0 + 3*CIN + k));
                a00 += dot4(x0v, w0v); a01 += dot4(x0v, w1v);
                a10 += dot4(x1v, w0v); a11 += dot4(x1v, w1v);
                a20 += dot4(x2v, w0v); a21 += dot4(x2v, w1v);
                a30 += dot4(x3v, w0v); a31 += dot4(x3v, w1v);
            }
            float* o = g_xw + (size_t)r0 * HH;
            o[lane] = a00;        o[lane+32] = a01;
            o[HH+lane] = a10;     o[HH+lane+32] = a11;
            o[2*HH+lane] = a20;   o[2*HH+lane+32] = a21;
            o[3*HH+lane] = a30;   o[3*HH+lane+32] = a31;
        }
    }
    gsync();

    // ============ PC: block0 scan || others dis ============
    if (bid == 0) {
        int* wsum = (int*)shbuf;
        int base = tid * 16;
        int local[16];
        int s = 0;
        #pragma unroll
        for (int i = 0; i < 16; i++) { local[i] = g_cnt[base + i]; s += local[i]; }
        int ws = s;
        #pragma unroll
        for (int o = 1; o < 32; o <<= 1) {
            int v = __shfl_up_sync(0xFFFFFFFFu, ws, o);
            if (lane >= o) ws += v;
        }
        if (lane == 31) wsum[wid] = ws;
        __syncthreads();
        if (tid < 32) {
            int v = wsum[tid];
            #pragma unroll
            for (int o = 1; o < 32; o <<= 1) {
                int u = __shfl_up_sync(0xFFFFFFFFu, v, o);
                if (tid >= o) v += u;
            }
            wsum[tid] = v;
        }
        __syncthreads();
        int run = (wid ? wsum[wid - 1] : 0) + ws - s;
        #pragma unroll
        for (int i = 0; i < 16; i++) {
            g_off[base + i] = run;
            g_cur[base + i] = run;
            run += local[i];
        }
        if (tid == NT - 1) g_off[Nn] = run;
    } else {
        for (int j = (bid - 1) * NT + tid; j < Nn; j += (gridDim.x - 1) * NT)
            g_dis[j] = rsqrtf(g_deg[j]);
    }
    gsync();

    // ============ PD: fill buckets with normalized weight ============
    for (int e = gt; e < E; e += nth) {
        int r = __ldg(ei + e);
        int c = __ldg(ei + E + e);
        float wn = g_dis[r] * __ldg(ew + e) * g_dis[c];
        int pos = atomicAdd(&g_cur[c], 1);
        g_ed[pos] = ((unsigned long long)__float_as_uint(wn) << 32) | (unsigned)r;
    }
    gsync();

    // ============ PE: gather + self loop + bias + relu (work-steal) ============
    {
        const float4* xw4 = (const float4*)g_xw;
        float4* h4 = (float4*)g_h;
        float4 bb = __ldg((const float4*)b1 + l16);
        for (;;) {
            int p = 0;
            if (l16 == 0) p = (int)atomicAdd(&g_ws0, 1u);
            int c = __shfl_sync(hmask, p, hsrc);
            if (c >= Nn) break;
            int beg = g_off[c], end = g_off[c + 1];
            float dc = g_dis[c];
            float sw = dc * dc;
            float4 acc = xw4[c*16 + l16];
            acc.x *= sw; acc.y *= sw; acc.z *= sw; acc.w *= sw;
            int j = beg;
            for (; j + 4 <= end; j += 4) {
                unsigned long long p0 = __ldg(g_ed + j);
                unsigned long long p1 = __ldg(g_ed + j + 1);
                unsigned long long p2 = __ldg(g_ed + j + 2);
                unsigned long long p3 = __ldg(g_ed + j + 3);
                int r0 = (int)(unsigned)p0, r1 = (int)(unsigned)p1;
                int r2 = (int)(unsigned)p2, r3 = (int)(unsigned)p3;
                float w0 = __uint_as_float((unsigned)(p0 >> 32));
                float w1 = __uint_as_float((unsigned)(p1 >> 32));
                float w2 = __uint_as_float((unsigned)(p2 >> 32));
                float w3 = __uint_as_float((unsigned)(p3 >> 32));
                float4 v0 = xw4[r0*16 + l16];
                float4 v1 = xw4[r1*16 + l16];
                float4 v2 = xw4[r2*16 + l16];
                float4 v3 = xw4[r3*16 + l16];
                acc.x += w0*v0.x + w1*v1.x + w2*v2.x + w3*v3.x;
                acc.y += w0*v0.y + w1*v1.y + w2*v2.y + w3*v3.y;
                acc.z += w0*v0.z + w1*v1.z + w2*v2.z + w3*v3.z;
                acc.w += w0*v0.w + w1*v1.w + w2*v2.w + w3*v3.w;
            }
            for (; j < end; j++) {
                unsigned long long p = __ldg(g_ed + j);
                int r = (int)(unsigned)p;
                float w = __uint_as_float((unsigned)(p >> 32));
                float4 v = xw4[r*16 + l16];
                acc.x += w*v.x; acc.y += w*v.y; acc.z += w*v.z; acc.w += w*v.w;
            }
            acc.x = fmaxf(acc.x + bb.x, 0.f);
            acc.y = fmaxf(acc.y + bb.y, 0.f);
            acc.z = fmaxf(acc.z + bb.z, 0.f);
            acc.w = fmaxf(acc.w + bb.w, 0.f);
            h4[c*16 + l16] = acc;
        }
        __syncwarp();
    }
    gsync();

    // ============ PF: collapsed MLP + softmax + cs/ca ============
    {
        // stage g_W transposed: shbuf[c*68 + k] = g_W[k*KK + c]
        for (int j = tid; j < HH*KK; j += NT)
            shbuf[(j & 63) * 68 + (j >> 6)] = g_W[j];
        __syncthreads();
        const float* wp0 = shbuf + lane * 68;
        const float* wp1 = shbuf + (lane + 32) * 68;
        float b2a = g_bb[lane], b2b = g_bb[lane + 32];
        float cs0 = 0.f, cs1 = 0.f, ca0 = 0.f, ca1 = 0.f;
        for (int r0 = gwarp * 2; r0 < Nn; r0 += nwarp * 2) {
            const float* h0 = g_h + (size_t)r0 * HH;
            const float* h1 = h0 + HH;
            float l00 = b2a, l01 = b2b, l10 = b2a, l11 = b2b;
            #pragma unroll 4
            for (int k = 0; k < HH; k += 4) {
                float4 wa = *(const float4*)(wp0 + k);
                float4 wb = *(const float4*)(wp1 + k);
                float4 ha = __ldg((const float4*)(h0 + k));
                float4 hb = __ldg((const float4*)(h1 + k));
                l00 += dot4(ha, wa); l01 += dot4(ha, wb);
                l10 += dot4(hb, wa); l11 += dot4(hb, wb);
            }
            // two softmaxes, interleaved reductions
            float mx0 = fmaxf(l00, l01);
            float mx1 = fmaxf(l10, l11);
            #pragma unroll
            for (int o = 16; o; o >>= 1) {
                mx0 = fmaxf(mx0, __shfl_xor_sync(0xFFFFFFFFu, mx0, o));
                mx1 = fmaxf(mx1, __shfl_xor_sync(0xFFFFFFFFu, mx1, o));
            }
            float e00 = __expf(l00 - mx0), e01 = __expf(l01 - mx0);
            float e10 = __expf(l10 - mx1), e11 = __expf(l11 - mx1);
            float sm0 = e00 + e01, sm1 = e10 + e11;
            #pragma unroll
            for (int o = 16; o; o >>= 1) {
                sm0 += __shfl_xor_sync(0xFFFFFFFFu, sm0, o);
                sm1 += __shfl_xor_sync(0xFFFFFFFFu, sm1, o);
            }
            float i0 = 1.0f / sm0, i1 = 1.0f / sm1;
            float s00 = e00 * i0, s01 = e01 * i0;
            float s10 = e10 * i1, s11 = e11 * i1;
            out[(size_t)r0*KK + lane]          = s00;
            out[(size_t)r0*KK + lane + 32]     = s01;
            out[(size_t)(r0+1)*KK + lane]      = s10;
            out[(size_t)(r0+1)*KK + lane + 32] = s11;
            cs0 += s00 + s10; cs1 += s01 + s11;
            float da0 = (float)g_cnt[r0];
            float da1 = (float)g_cnt[r0 + 1];
            ca0 += s00 * da0 + s10 * da1;
            ca1 += s01 * da0 + s11 * da1;
        }
        atomicAdd(&g_cs[lane], cs0); atomicAdd(&g_cs[lane + 32], cs1);
        atomicAdd(&g_ca[lane], ca0); atomicAdd(&g_ca[lane + 32], ca1);
    }
    gsync();

    // ============ PG: ss = s^T s AND trace(s^T A s) ============
    {
        if (tid == 0) tr_part = 0.f;
        // --- ss: 16 rows per block-chunk ---
        float* srows = shbuf;  // 1024 floats
        int a = tid >> 4, q = tid & 15;
        float ac0=0, ac1=0, ac2=0, ac3=0;
        for (int base = bid * 16; base < Nn; base += gridDim.x * 16) {
            __syncthreads();
            if (tid < 256) ((float4*)srows)[tid] = ((const float4*)(out + (size_t)base*KK))[tid];
            __syncthreads();
            #pragma unroll
            for (int r = 0; r < 16; r++) {
                float sa = srows[r*KK + a];
                float4 vb = ((const float4*)(srows + r*KK))[q];
                ac0 += sa * vb.x; ac1 += sa * vb.y;
                ac2 += sa * vb.z; ac3 += sa * vb.w;
            }
        }
        atomicAdd(&g_ss[a*KK + q*4 + 0], ac0);
        atomicAdd(&g_ss[a*KK + q*4 + 1], ac1);
        atomicAdd(&g_ss[a*KK + q*4 + 2], ac2);
        atomicAdd(&g_ss[a*KK + q*4 + 3], ac3);
        __syncthreads();

        // --- trace via buckets: 16 lanes per node, work-steal ---
        const float4* s4 = (const float4*)out;
        float tacc = 0.f;
        for (;;) {
            int p = 0;
            if (l16 == 0) p = (int)atomicAdd(&g_ws1, 1u);
            int c = __shfl_sync(hmask, p, hsrc);
            if (c >= Nn) break;
            int beg = g_off[c], end = g_off[c + 1];
            float4 sc = s4[c*16 + l16];
            int j = beg;
            for (; j + 4 <= end; j += 4) {
                int r0 = (int)(unsigned)__ldg(g_ed + j);
                int r1 = (int)(unsigned)__ldg(g_ed + j + 1);
                int r2 = (int)(unsigned)__ldg(g_ed + j + 2);
                int r3 = (int)(unsigned)__ldg(g_ed + j + 3);
                float4 v0 = s4[r0*16 + l16];
                float4 v1 = s4[r1*16 + l16];
                float4 v2 = s4[r2*16 + l16];
                float4 v3 = s4[r3*16 + l16];
                tacc += v0.x*sc.x + v0.y*sc.y + v0.z*sc.z + v0.w*sc.w;
                tacc += v1.x*sc.x + v1.y*sc.y + v1.z*sc.z + v1.w*sc.w;
                tacc += v2.x*sc.x + v2.y*sc.y + v2.z*sc.z + v2.w*sc.w;
                tacc += v3.x*sc.x + v3.y*sc.y + v3.z*sc.z + v3.w*sc.w;
            }
            for (; j < end; j++) {
                int r = (int)(unsigned)__ldg(g_ed + j);
                float4 v = s4[r*16 + l16];
                tacc += v.x*sc.x + v.y*sc.y + v.z*sc.z + v.w*sc.w;
            }
        }
        __syncwarp();
        #pragma unroll
        for (int o = 16; o; o >>= 1) tacc += __shfl_xor_sync(0xFFFFFFFFu, tacc, o);
        if (lane == 0) atomicAdd(&tr_part, tacc);
        __syncthreads();
        if (tid == 0) atomicAdd(&g_trace, (double)tr_part);
    }
    gsync();

    // ============ PH: final loss (block 0) ============
    if (bid == 0) {
        float* red = shbuf;
        float v;

        v = 0.f;
        for (int i = tid; i < KK; i += NT) v += g_ca[i] * g_ca[i];
        red[tid] = v; __syncthreads();
        for (int o = NT/2; o; o >>= 1) { if (tid < o) red[tid] += red[tid + o]; __syncthreads(); }
        float ca2 = red[0]; __syncthreads();

        v = 0.f;
        for (int i = tid; i < KK*KK; i += NT) { float u = g_ss[i]; v += u * u; }
        red[tid] = v; __syncthreads();
        for (int o = NT/2; o; o >>= 1) { if (tid < o) red[tid] += red[tid + o]; __syncthreads(); }
        float ss2 = red[0]; __syncthreads();

        v = 0.f;
        for (int i = tid; i < KK; i += NT) v += g_ss[i*KK + i];
        red[tid] = v; __syncthreads();
        for (int o = NT/2; o; o >>= 1) { if (tid < o) red[tid] += red[tid + o]; __syncthreads(); }
        float trss = red[0]; __syncthreads();

        v = 0.f;
        for (int i = tid; i < KK; i += NT) v += g_cs[i] * g_cs[i];
        red[tid] = v; __syncthreads();
        for (int o = NT/2; o; o >>= 1) { if (tid < o) red[tid] += red[tid + o]; __syncthreads(); }
        float cs2 = red[0]; __syncthreads();

        if (tid == 0) {
            float two_m = (float)E;
            float tr_out = (float)g_trace;
            float spectral = -(tr_out - ca2 / two_m) / two_m;
            float ssfro = sqrtf(ss2);
            float ortho = sqrtf(fmaxf(2.0f - trss / (4.0f * ssfro), 0.0f));
            float cluster = sqrtf(cs2) / (float)Nn * 8.0f - 1.0f;
            float loss = spectral + ortho + cluster;
            for (int i = Nn*KK; i < out_size; i++) out[i] = loss;
        }
    }
}

// ---------------- launch ----------------
extern "C" void kernel_launch(void* const* d_in, const int* in_sizes, int n_in,
                              void* d_out, int out_size) {
    const float* x   = (const float*)d_in[0];
    const int*   ei  = (const int*)d_in[1];
    const float* ew  = (const float*)d_in[2];
    const float* W1  = (const float*)d_in[3];
    const float* b1  = (const float*)d_in[4];
    const float* Wm1 = (const float*)d_in[5];
    const float* bm1 = (const float*)d_in[6];
    const float* Wm2 = (const float*)d_in[7];
    const float* bm2 = (const float*)d_in[8];
    float* out = (float*)d_out;
    int E = in_sizes[2];

    int nsm = 148;
    cudaDeviceGetAttribute(&nsm, cudaDevAttrMultiProcessorCount, 0);
    if (nsm < 2) nsm = 148;
    if (nsm > 512) nsm = 512;

    mega<<<nsm, NT>>>(x, ei, ew, W1, b1, Wm1, bm1, Wm2, bm2, out, E, out_size);
}

// round 6
// speedup vs baseline: 1.3113x; 1.0544x over previous
#include <cuda_runtime.h>

#define Nn 16384
#define EE 524288
#define CIN 128
#define HH 64
#define KK 64
#define NT 1024

// ---------------- device scratch (zero-restore invariant: every replay
// leaves these in the same state it found them) ----------------
__device__ float g_xw[Nn*HH];
__device__ float g_h[Nn*HH];
__device__ float g_dis[Nn];
__device__ float g_deg[Nn];                // 0 at entry; zeroed in PD
__device__ int   g_cnt[Nn];                // 0 at entry; zeroed in PG
__device__ int   g_off[Nn+1];
__device__ int   g_cur[Nn];
__device__ unsigned long long g_ed[EE+8];  // +8 pad (never written; stays 0)
__device__ float g_W[HH*KK];
__device__ float g_bb[KK];
__device__ float g_ss[KK*KK];              // zeroed in PH
__device__ float g_ca[KK];                 // zeroed in PH
__device__ float g_cs[KK];                 // zeroed in PH
__device__ double g_trace;                 // zeroed in PH
__device__ unsigned g_bar_cnt, g_bar_gen;
__device__ unsigned g_ws0, g_ws1, g_ws2, g_ws3;  // steal cursors

__device__ __forceinline__ void gsync() {
    __syncthreads();
    if (threadIdx.x == 0) {
        volatile unsigned* genp = &g_bar_gen;
        unsigned gen = *genp;
        __threadfence();
        if (atomicAdd(&g_bar_cnt, 1u) == gridDim.x - 1) {
            g_bar_cnt = 0;
            __threadfence();
            atomicAdd(&g_bar_gen, 1u);
        } else {
            while (*genp == gen) __nanosleep(32);
        }
        __threadfence();
    }
    __syncthreads();
}

__device__ __forceinline__ float dot4(float4 a, float4 b) {
    return a.x*b.x + a.y*b.y + a.z*b.z + a.w*b.w;
}

__global__ void __launch_bounds__(NT, 1)
mega(const float* __restrict__ x, const int* __restrict__ ei,
     const float* __restrict__ ew,
     const float* __restrict__ W1, const float* __restrict__ b1,
     const float* __restrict__ Wm1, const float* __restrict__ bm1,
     const float* __restrict__ Wm2, const float* __restrict__ bm2,
     float* __restrict__ out, int E, int out_size)
{
    __shared__ float shbuf[8704];   // 34 KB, re-carved per phase
    __shared__ float tr_part;
    const int tid = threadIdx.x, bid = blockIdx.x;
    const int nth = gridDim.x * NT;
    const int gt = bid * NT + tid;
    const int lane = tid & 31, wid = tid >> 5;
    const int l16 = lane & 15;
    const unsigned hmask = 0xFFFFu << (lane & 16);
    const int hsrc = lane & 16;

    // ============ PB: edge histogram + W-collapse + xw GEMM (stolen) ============
    for (int j = tid; j < CIN*HH; j += NT)
        shbuf[(j & 63) * 132 + (j >> 6)] = W1[j];

    for (int e = gt; e < E; e += nth) {
        int c = __ldg(ei + E + e);
        atomicAdd(&g_deg[c], __ldg(ew + e));
        atomicAdd(&g_cnt[c], 1);
    }

    if (bid == 0) {
        // g_W[k][c] = sum_j Wm1[k][j] * Wm2[j][c];  g_bb = bm1@Wm2 + bm2
        int a = tid >> 4;
        int c0 = (tid & 15) * 4;
        float4 acc = make_float4(0.f, 0.f, 0.f, 0.f);
        #pragma unroll 8
        for (int j = 0; j < HH; j++) {
            float m = __ldg(Wm1 + a*HH + j);
            float4 w2 = __ldg((const float4*)(Wm2 + j*KK + c0));
            acc.x += m * w2.x; acc.y += m * w2.y;
            acc.z += m * w2.z; acc.w += m * w2.w;
        }
        ((float4*)g_W)[tid] = acc;
        if (tid < KK) {
            float b = __ldg(bm2 + tid);
            for (int j = 0; j < HH; j++) b += __ldg(bm1 + j) * __ldg(Wm2 + j*KK + tid);
            g_bb[tid] = b;
        }
    }
    __syncthreads();

    // xw GEMM: warp steals chunks of 4 rows
    for (;;) {
        int p = 0;
        if (lane == 0) p = (int)atomicAdd(&g_ws2, 1u);
        p = __shfl_sync(0xFFFFFFFFu, p, 0);
        int r0 = p * 4;
        if (r0 >= Nn) break;
        float a00=0,a01=0,a10=0,a11=0,a20=0,a21=0,a30=0,a31=0;
        const float* x0 = x + (size_t)r0 * CIN;
        const float* wp0 = shbuf + lane * 132;
        const float* wp1 = shbuf + (lane + 32) * 132;
        #pragma unroll 4
        for (int k = 0; k < CIN; k += 4) {
            float4 w0v = *(const float4*)(wp0 + k);
            float4 w1v = *(const float4*)(wp1 + k);
            float4 x0v = __ldg((const float4*)(x0 + k));
            float4 x1v = __ldg((const float4*)(x0 + CIN + k));
            float4 x2v = __ldg((const float4*)(x0 + 2*CIN + k));
            float4 x3v = __ldg((const float4*)(x0 + 3*CIN + k));
            a00 += dot4(x0v, w0v); a01 += dot4(x0v, w1v);
            a10 += dot4(x1v, w0v); a11 += dot4(x1v, w1v);
            a20 += dot4(x2v, w0v); a21 += dot4(x2v, w1v);
            a30 += dot4(x3v, w0v); a31 += dot4(x3v, w1v);
        }
        float* o = g_xw + (size_t)r0 * HH;
        o[lane] = a00;        o[lane+32] = a01;
        o[HH+lane] = a10;     o[HH+lane+32] = a11;
        o[2*HH+lane] = a20;   o[2*HH+lane+32] = a21;
        o[3*HH+lane] = a30;   o[3*HH+lane+32] = a31;
    }
    gsync();

    // ============ PC: block0 scan || others dis ============
    if (bid == 0) {
        int* wsum = (int*)shbuf;
        int base = tid * 16;
        int local[16];
        int s = 0;
        #pragma unroll
        for (int i = 0; i < 16; i++) { local[i] = g_cnt[base + i]; s += local[i]; }
        int ws = s;
        #pragma unroll
        for (int o = 1; o < 32; o <<= 1) {
            int v = __shfl_up_sync(0xFFFFFFFFu, ws, o);
            if (lane >= o) ws += v;
        }
        if (lane == 31) wsum[wid] = ws;
        __syncthreads();
        if (tid < 32) {
            int v = wsum[tid];
            #pragma unroll
            for (int o = 1; o < 32; o <<= 1) {
                int u = __shfl_up_sync(0xFFFFFFFFu, v, o);
                if (tid >= o) v += u;
            }
            wsum[tid] = v;
        }
        __syncthreads();
        int run = (wid ? wsum[wid - 1] : 0) + ws - s;
        #pragma unroll
        for (int i = 0; i < 16; i++) {
            g_off[base + i] = run;
            g_cur[base + i] = run;
            run += local[i];
        }
        if (tid == NT - 1) g_off[Nn] = run;
    } else {
        for (int j = (bid - 1) * NT + tid; j < Nn; j += (gridDim.x - 1) * NT)
            g_dis[j] = rsqrtf(g_deg[j] + 1.0f);   // +1 self loop
    }
    gsync();

    // ============ PD: fill buckets + restore g_deg/g_ws2 ============
    for (int j = gt; j < Nn; j += nth) g_deg[j] = 0.f;
    if (gt == 0) g_ws2 = 0u;
    for (int e = gt; e < E; e += nth) {
        int r = __ldg(ei + e);
        int c = __ldg(ei + E + e);
        float wn = g_dis[r] * __ldg(ew + e) * g_dis[c];
        int pos = atomicAdd(&g_cur[c], 1);
        g_ed[pos] = ((unsigned long long)__float_as_uint(wn) << 32) | (unsigned)r;
    }
    gsync();

    // ============ PE: gather + self loop + bias + relu (steal, 8-deep) ============
    {
        const float4* xw4 = (const float4*)g_xw;
        float4* h4 = (float4*)g_h;
        float4 bb = __ldg((const float4*)b1 + l16);
        for (;;) {
            int p = 0;
            if (l16 == 0) p = (int)atomicAdd(&g_ws0, 1u);
            int c = __shfl_sync(hmask, p, hsrc);
            if (c >= Nn) break;
            int beg = g_off[c], end = g_off[c + 1];
            float dc = g_dis[c];
            float sw = dc * dc;
            float4 acc = xw4[c*16 + l16];
            acc.x *= sw; acc.y *= sw; acc.z *= sw; acc.w *= sw;
            for (int j = beg; j < end; j += 8) {
                unsigned long long p0 = __ldg(g_ed + j + 0);
                unsigned long long p1 = __ldg(g_ed + j + 1);
                unsigned long long p2 = __ldg(g_ed + j + 2);
                unsigned long long p3 = __ldg(g_ed + j + 3);
                unsigned long long p4 = __ldg(g_ed + j + 4);
                unsigned long long p5 = __ldg(g_ed + j + 5);
                unsigned long long p6 = __ldg(g_ed + j + 6);
                unsigned long long p7 = __ldg(g_ed + j + 7);
                int r0 = (int)(unsigned)p0, r1 = (int)(unsigned)p1;
                int r2 = (int)(unsigned)p2, r3 = (int)(unsigned)p3;
                int r4 = (int)(unsigned)p4, r5 = (int)(unsigned)p5;
                int r6 = (int)(unsigned)p6, r7 = (int)(unsigned)p7;
                float w0 =              __uint_as_float((unsigned)(p0 >> 32));
                float w1 = (j+1 < end)? __uint_as_float((unsigned)(p1 >> 32)) : 0.f;
                float w2 = (j+2 < end)? __uint_as_float((unsigned)(p2 >> 32)) : 0.f;
                float w3 = (j+3 < end)? __uint_as_float((unsigned)(p3 >> 32)) : 0.f;
                float w4 = (j+4 < end)? __uint_as_float((unsigned)(p4 >> 32)) : 0.f;
                float w5 = (j+5 < end)? __uint_as_float((unsigned)(p5 >> 32)) : 0.f;
                float w6 = (j+6 < end)? __uint_as_float((unsigned)(p6 >> 32)) : 0.f;
                float w7 = (j+7 < end)? __uint_as_float((unsigned)(p7 >> 32)) : 0.f;
                float4 v0 = xw4[r0*16 + l16];
                float4 v1 = xw4[r1*16 + l16];
                float4 v2 = xw4[r2*16 + l16];
                float4 v3 = xw4[r3*16 + l16];
                float4 v4 = xw4[r4*16 + l16];
                float4 v5 = xw4[r5*16 + l16];
                float4 v6 = xw4[r6*16 + l16];
                float4 v7 = xw4[r7*16 + l16];
                acc.x += w0*v0.x + w1*v1.x + w2*v2.x + w3*v3.x
                       + w4*v4.x + w5*v5.x + w6*v6.x + w7*v7.x;
                acc.y += w0*v0.y + w1*v1.y + w2*v2.y + w3*v3.y
                       + w4*v4.y + w5*v5.y + w6*v6.y + w7*v7.y;
                acc.z += w0*v0.z + w1*v1.z + w2*v2.z + w3*v3.z
                       + w4*v4.z + w5*v5.z + w6*v6.z + w7*v7.z;
                acc.w += w0*v0.w + w1*v1.w + w2*v2.w + w3*v3.w
                       + w4*v4.w + w5*v5.w + w6*v6.w + w7*v7.w;
            }
            acc.x = fmaxf(acc.x + bb.x, 0.f);
            acc.y = fmaxf(acc.y + bb.y, 0.f);
            acc.z = fmaxf(acc.z + bb.z, 0.f);
            acc.w = fmaxf(acc.w + bb.w, 0.f);
            h4[c*16 + l16] = acc;
        }
        __syncwarp();
    }
    gsync();

    // ============ PF: collapsed MLP + softmax + cs/ca (steal, 2 rows/chunk) ============
    {
        if (gt == 0) g_ws0 = 0u;
        for (int j = tid; j < HH*KK; j += NT)
            shbuf[(j & 63) * 68 + (j >> 6)] = g_W[j];
        __syncthreads();
        const float* wp0 = shbuf + lane * 68;
        const float* wp1 = shbuf + (lane + 32) * 68;
        float b2a = g_bb[lane], b2b = g_bb[lane + 32];
        float cs0 = 0.f, cs1 = 0.f, ca0 = 0.f, ca1 = 0.f;
        for (;;) {
            int p = 0;
            if (lane == 0) p = (int)atomicAdd(&g_ws3, 1u);
            p = __shfl_sync(0xFFFFFFFFu, p, 0);
            int r0 = p * 2;
            if (r0 >= Nn) break;
            const float* h0 = g_h + (size_t)r0 * HH;
            const float* h1 = h0 + HH;
            float l00 = b2a, l01 = b2b, l10 = b2a, l11 = b2b;
            #pragma unroll 4
            for (int k = 0; k < HH; k += 4) {
                float4 wa = *(const float4*)(wp0 + k);
                float4 wb = *(const float4*)(wp1 + k);
                float4 ha = __ldg((const float4*)(h0 + k));
                float4 hb = __ldg((const float4*)(h1 + k));
                l00 += dot4(ha, wa); l01 += dot4(ha, wb);
                l10 += dot4(hb, wa); l11 += dot4(hb, wb);
            }
            float mx0 = fmaxf(l00, l01);
            float mx1 = fmaxf(l10, l11);
            #pragma unroll
            for (int o = 16; o; o >>= 1) {
                mx0 = fmaxf(mx0, __shfl_xor_sync(0xFFFFFFFFu, mx0, o));
                mx1 = fmaxf(mx1, __shfl_xor_sync(0xFFFFFFFFu, mx1, o));
            }
            float e00 = __expf(l00 - mx0), e01 = __expf(l01 - mx0);
            float e10 = __expf(l10 - mx1), e11 = __expf(l11 - mx1);
            float sm0 = e00 + e01, sm1 = e10 + e11;
            #pragma unroll
            for (int o = 16; o; o >>= 1) {
                sm0 += __shfl_xor_sync(0xFFFFFFFFu, sm0, o);
                sm1 += __shfl_xor_sync(0xFFFFFFFFu, sm1, o);
            }
            float i0 = 1.0f / sm0, i1 = 1.0f / sm1;
            float s00 = e00 * i0, s01 = e01 * i0;
            float s10 = e10 * i1, s11 = e11 * i1;
            out[(size_t)r0*KK + lane]          = s00;
            out[(size_t)r0*KK + lane + 32]     = s01;
            out[(size_t)(r0+1)*KK + lane]      = s10;
            out[(size_t)(r0+1)*KK + lane + 32] = s11;
            cs0 += s00 + s10; cs1 += s01 + s11;
            float da0 = (float)g_cnt[r0];
            float da1 = (float)g_cnt[r0 + 1];
            ca0 += s00 * da0 + s10 * da1;
            ca1 += s01 * da0 + s11 * da1;
        }
        atomicAdd(&g_cs[lane], cs0); atomicAdd(&g_cs[lane + 32], cs1);
        atomicAdd(&g_ca[lane], ca0); atomicAdd(&g_ca[lane + 32], ca1);
    }
    gsync();

    // ============ PG: restore cnt/ws3 + ss = s^T s + trace (steal, 8-deep) ============
    {
        if (tid == 0) tr_part = 0.f;
        for (int j = gt; j < Nn; j += nth) g_cnt[j] = 0;
        if (gt == 0) g_ws3 = 0u;

        // --- ss: 16 rows per block-chunk ---
        float* srows = shbuf;
        int a = tid >> 4, q = tid & 15;
        float ac0=0, ac1=0, ac2=0, ac3=0;
        for (int base = bid * 16; base < Nn; base += gridDim.x * 16) {
            __syncthreads();
            if (tid < 256) ((float4*)srows)[tid] = ((const float4*)(out + (size_t)base*KK))[tid];
            __syncthreads();
            #pragma unroll
            for (int r = 0; r < 16; r++) {
                float sa = srows[r*KK + a];
                float4 vb = ((const float4*)(srows + r*KK))[q];
                ac0 += sa * vb.x; ac1 += sa * vb.y;
                ac2 += sa * vb.z; ac3 += sa * vb.w;
            }
        }
        atomicAdd(&g_ss[a*KK + q*4 + 0], ac0);
        atomicAdd(&g_ss[a*KK + q*4 + 1], ac1);
        atomicAdd(&g_ss[a*KK + q*4 + 2], ac2);
        atomicAdd(&g_ss[a*KK + q*4 + 3], ac3);
        __syncthreads();

        // --- trace via buckets: half-warp per node, 8-deep, steal ---
        const float4* s4 = (const float4*)out;
        float tacc = 0.f;
        for (;;) {
            int p = 0;
            if (l16 == 0) p = (int)atomicAdd(&g_ws1, 1u);
            int c = __shfl_sync(hmask, p, hsrc);
            if (c >= Nn) break;
            int beg = g_off[c], end = g_off[c + 1];
            float4 sc = s4[c*16 + l16];
            for (int j = beg; j < end; j += 8) {
                int r0 = (int)(unsigned)__ldg(g_ed + j + 0);
                int r1 = (int)(unsigned)__ldg(g_ed + j + 1);
                int r2 = (int)(unsigned)__ldg(g_ed + j + 2);
                int r3 = (int)(unsigned)__ldg(g_ed + j + 3);
                int r4 = (int)(unsigned)__ldg(g_ed + j + 4);
                int r5 = (int)(unsigned)__ldg(g_ed + j + 5);
                int r6 = (int)(unsigned)__ldg(g_ed + j + 6);
                int r7 = (int)(unsigned)__ldg(g_ed + j + 7);
                float m1 = (j+1 < end) ? 1.f : 0.f;
                float m2 = (j+2 < end) ? 1.f : 0.f;
                float m3 = (j+3 < end) ? 1.f : 0.f;
                float m4 = (j+4 < end) ? 1.f : 0.f;
                float m5 = (j+5 < end) ? 1.f : 0.f;
                float m6 = (j+6 < end) ? 1.f : 0.f;
                float m7 = (j+7 < end) ? 1.f : 0.f;
                float4 v0 = s4[r0*16 + l16];
                float4 v1 = s4[r1*16 + l16];
                float4 v2 = s4[r2*16 + l16];
                float4 v3 = s4[r3*16 + l16];
                float4 v4 = s4[r4*16 + l16];
                float4 v5 = s4[r5*16 + l16];
                float4 v6 = s4[r6*16 + l16];
                float4 v7 = s4[r7*16 + l16];
                tacc +=      dot4(v0, sc);
                tacc += m1 * dot4(v1, sc);
                tacc += m2 * dot4(v2, sc);
                tacc += m3 * dot4(v3, sc);
                tacc += m4 * dot4(v4, sc);
                tacc += m5 * dot4(v5, sc);
                tacc += m6 * dot4(v6, sc);
                tacc += m7 * dot4(v7, sc);
            }
        }
        __syncwarp();
        #pragma unroll
        for (int o = 16; o; o >>= 1) tacc += __shfl_xor_sync(0xFFFFFFFFu, tacc, o);
        if (lane == 0) atomicAdd(&tr_part, tacc);
        __syncthreads();
        if (tid == 0) atomicAdd(&g_trace, (double)tr_part);
    }
    gsync();

    // ============ PH: final loss (block 0) + restore accumulators ============
    if (bid == 0) {
        float* red = shbuf;
        float v;

        v = 0.f;
        for (int i = tid; i < KK; i += NT) v += g_ca[i] * g_ca[i];
        red[tid] = v; __syncthreads();
        for (int o = NT/2; o; o >>= 1) { if (tid < o) red[tid] += red[tid + o]; __syncthreads(); }
        float ca2 = red[0]; __syncthreads();

        v = 0.f;
        for (int i = tid; i < KK*KK; i += NT) { float u = g_ss[i]; v += u * u; }
        red[tid] = v; __syncthreads();
        for (int o = NT/2; o; o >>= 1) { if (tid < o) red[tid] += red[tid + o]; __syncthreads(); }
        float ss2 = red[0]; __syncthreads();

        v = 0.f;
        for (int i = tid; i < KK; i += NT) v += g_ss[i*KK + i];
        red[tid] = v; __syncthreads();
        for (int o = NT/2; o; o >>= 1) { if (tid < o) red[tid] += red[tid + o]; __syncthreads(); }
        float trss = red[0]; __syncthreads();

        v = 0.f;
        for (int i = tid; i < KK; i += NT) v += g_cs[i] * g_cs[i];
        red[tid] = v; __syncthreads();
        for (int o = NT/2; o; o >>= 1) { if (tid < o) red[tid] += red[tid + o]; __syncthreads(); }
        float cs2 = red[0]; __syncthreads();

        if (tid == 0) {
            float two_m = (float)E;
            float tr_out = (float)g_trace;
            float spectral = -(tr_out - ca2 / two_m) / two_m;
            float ssfro = sqrtf(ss2);
            float ortho = sqrtf(fmaxf(2.0f - trss / (4.0f * ssfro), 0.0f));
            float cluster = sqrtf(cs2) / (float)Nn * 8.0f - 1.0f;
            float loss = spectral + ortho + cluster;
            for (int i = Nn*KK; i < out_size; i++) out[i] = loss;
            g_trace = 0.0;
            g_ws1 = 0u;
        }
        __syncthreads();
        // restore accumulators for next replay
        for (int i = tid; i < KK*KK; i += NT) g_ss[i] = 0.f;
        if (tid < KK) { g_ca[tid] = 0.f; g_cs[tid] = 0.f; }
    }
}

// ---------------- launch ----------------
extern "C" void kernel_launch(void* const* d_in, const int* in_sizes, int n_in,
                              void* d_out, int out_size) {
    const float* x   = (const float*)d_in[0];
    const int*   ei  = (const int*)d_in[1];
    const float* ew  = (const float*)d_in[2];
    const float* W1  = (const float*)d_in[3];
    const float* b1  = (const float*)d_in[4];
    const float* Wm1 = (const float*)d_in[5];
    const float* bm1 = (const float*)d_in[6];
    const float* Wm2 = (const float*)d_in[7];
    const float* bm2 = (const float*)d_in[8];
    float* out = (float*)d_out;
    int E = in_sizes[2];

    int nsm = 148;
    cudaDeviceGetAttribute(&nsm, cudaDevAttrMultiProcessorCount, 0);
    if (nsm < 2) nsm = 148;
    if (nsm > 512) nsm = 512;

    mega<<<nsm, NT>>>(x, ei, ew, W1, b1, Wm1, bm1, Wm2, bm2, out, E, out_size);
}